// round 10
// baseline (speedup 1.0000x reference)
#include <cuda_runtime.h>

// Shapes (fixed for this problem)
#define BB   8
#define LL   200
#define HIDD 256
#define NH   8
#define DHH  32
#define NEGV (-4294967295.0f)   // -2^32 + 1, matches reference padding value

// Scratch (device globals: allocation-free rule)
__device__ float g_Qp[BB * LL * HIDD];
__device__ float g_Ks[BB * LL * HIDD];   // K-proj + abs_pos_K  (folded)
__device__ float g_Vs[BB * LL * HIDD];   // V-proj + abs_pos_V  (folded)

// ---------------------------------------------------------------------------
// Projection GEMM:  Y = X @ W^T + bias (+ optional abs_pos fold)
// M=1600, N=256, K=256.  grid (25, 4, 3): z selects Q/K/V. block = 256 thr.
// ---------------------------------------------------------------------------
__global__ __launch_bounds__(256) void proj_kernel(
    const float* __restrict__ queries, const float* __restrict__ keys,
    const float* __restrict__ Wq, const float* __restrict__ bq,
    const float* __restrict__ Wk, const float* __restrict__ bk,
    const float* __restrict__ Wv, const float* __restrict__ bv,
    const float* __restrict__ apK, const float* __restrict__ apV)
{
    const int which = blockIdx.z;
    const float* X    = (which == 0) ? queries : keys;
    const float* W    = (which == 0) ? Wq : (which == 1) ? Wk : Wv;
    const float* bias = (which == 0) ? bq : (which == 1) ? bk : bv;
    const float* fold = (which == 0) ? (const float*)0 : (which == 1) ? apK : apV;
    float* Y          = (which == 0) ? g_Qp : (which == 1) ? g_Ks : g_Vs;

    __shared__ float As[16][65];   // [k][m], padded
    __shared__ float Bs[16][65];   // [k][n], padded

    const int tid = threadIdx.x;
    const int tx = tid & 15, ty = tid >> 4;
    const int row0 = blockIdx.x * 64, col0 = blockIdx.y * 64;

    const int lr  = tid >> 2;          // 0..63 (tile row to load)
    const int lc4 = (tid & 3) * 4;     // 0,4,8,12 (k-offset)

    float acc[4][4] = {};

    for (int kt = 0; kt < HIDD; kt += 16) {
        float4 av  = *(const float4*)&X[(row0 + lr) * HIDD + kt + lc4];
        float4 bv4 = *(const float4*)&W[(col0 + lr) * HIDD + kt + lc4];
        As[lc4 + 0][lr] = av.x;  As[lc4 + 1][lr] = av.y;
        As[lc4 + 2][lr] = av.z;  As[lc4 + 3][lr] = av.w;
        Bs[lc4 + 0][lr] = bv4.x; Bs[lc4 + 1][lr] = bv4.y;
        Bs[lc4 + 2][lr] = bv4.z; Bs[lc4 + 3][lr] = bv4.w;
        __syncthreads();
        #pragma unroll
        for (int kk = 0; kk < 16; kk++) {
            float a[4], b[4];
            #pragma unroll
            for (int i = 0; i < 4; i++) a[i] = As[kk][ty * 4 + i];
            #pragma unroll
            for (int j = 0; j < 4; j++) b[j] = Bs[kk][tx * 4 + j];
            #pragma unroll
            for (int i = 0; i < 4; i++)
                #pragma unroll
                for (int j = 0; j < 4; j++)
                    acc[i][j] += a[i] * b[j];
        }
        __syncthreads();
    }

    #pragma unroll
    for (int i = 0; i < 4; i++) {
        const int r = row0 + ty * 4 + i;
        #pragma unroll
        for (int j = 0; j < 4; j++) {
            const int cc = col0 + tx * 4 + j;
            float v = acc[i][j] + bias[cc];
            if (fold) v += fold[r * HIDD + cc];
            Y[r * HIDD + cc] = v;
        }
    }
}

// ---------------------------------------------------------------------------
// Attention: one CTA per (q-pair, b). 256 threads. TQ=2 queries per CTA.
// Phase 1: warp w handles k = w + 8i; lane holds 2 float4 of the shared Ksum
//   row (loaded once, used for both queries) + per-query TMk rows (__ldcs,
//   read-once streaming). Segmented 8-lane shuffle reduction -> 8 heads/pass.
// Phase 2: per-head softmax, warp-local, both queries.
// Phase 3: thread owns float4 channel group j, k strided mod 4; V row loaded
//   once per k, per-query TMv via __ldcs; zero-weight queries skipped.
// ---------------------------------------------------------------------------
__global__ __launch_bounds__(256, 4) void attn_kernel(
    const float* __restrict__ tmK, const float* __restrict__ tmV,
    const int* __restrict__ time_mask, const int* __restrict__ attn_mask,
    float* __restrict__ out)
{
    const int q0 = blockIdx.x * 2;
    const int q1 = q0 + 1;
    const int b  = blockIdx.y;
    const int tid = threadIdx.x;
    const int w = tid >> 5;        // warp
    const int l = tid & 31;        // lane

    __shared__ float aw[2][NH][LL];
    __shared__ int   mrow[2][LL];
    __shared__ float4 red[2][4][64];

    // Combined mask rows (nonzero word == true)
    const int tm0 = time_mask[b * LL + q0];
    const int tm1 = time_mask[b * LL + q1];
    for (int k = tid; k < LL; k += 256) {
        mrow[0][k] = (tm0 != 0) | (attn_mask[q0 * LL + k] != 0);
        mrow[1][k] = (tm1 != 0) | (attn_mask[q1 * LL + k] != 0);
    }
    __syncthreads();

    const float* __restrict__ Qp0 = g_Qp + (size_t)(b * LL + q0) * HIDD;
    const float* __restrict__ Qp1 = g_Qp + (size_t)(b * LL + q1) * HIDD;
    const float4 qa0 = *(const float4*)(Qp0 + 4 * l);
    const float4 qa1 = *(const float4*)(Qp0 + 128 + 4 * l);
    const float4 qb0 = *(const float4*)(Qp1 + 4 * l);
    const float4 qb1 = *(const float4*)(Qp1 + 128 + 4 * l);

    const float* __restrict__ Ks   = g_Ks + (size_t)(b * LL) * HIDD;
    const float* __restrict__ TMK0 = tmK + (size_t)(b * LL + q0) * LL * HIDD;
    const float* __restrict__ TMK1 = tmK + (size_t)(b * LL + q1) * LL * HIDD;
    const float  scale = 0.17677669529663687f;   // 1/sqrt(32)

    const int  seg = l >> 3;           // 0..3: p0 -> head seg, p1 -> head 4+seg
    const bool wr  = (l & 7) == 0;

    // ---- Phase 1: logits (25 k's per warp, both queries) ----
    #pragma unroll 2
    for (int i = 0; i < LL / 8; i++) {
        const int k = w + 8 * i;
        const int m0 = mrow[0][k], m1 = mrow[1][k];

        float4 a0, a1, t00, t01, t10, t11;
        if (!(m0 & m1)) {
            a0 = *(const float4*)(Ks + k * HIDD + 4 * l);
            a1 = *(const float4*)(Ks + k * HIDD + 128 + 4 * l);
        }
        if (!m0) {
            t00 = __ldcs((const float4*)(TMK0 + (size_t)k * HIDD + 4 * l));
            t01 = __ldcs((const float4*)(TMK0 + (size_t)k * HIDD + 128 + 4 * l));
        }
        if (!m1) {
            t10 = __ldcs((const float4*)(TMK1 + (size_t)k * HIDD + 4 * l));
            t11 = __ldcs((const float4*)(TMK1 + (size_t)k * HIDD + 128 + 4 * l));
        }

        if (!m0) {
            float p0 = qa0.x * (a0.x + t00.x) + qa0.y * (a0.y + t00.y)
                     + qa0.z * (a0.z + t00.z) + qa0.w * (a0.w + t00.w);
            float p1 = qa1.x * (a1.x + t01.x) + qa1.y * (a1.y + t01.y)
                     + qa1.z * (a1.z + t01.z) + qa1.w * (a1.w + t01.w);
            p0 += __shfl_xor_sync(0xffffffffu, p0, 1);
            p0 += __shfl_xor_sync(0xffffffffu, p0, 2);
            p0 += __shfl_xor_sync(0xffffffffu, p0, 4);
            p1 += __shfl_xor_sync(0xffffffffu, p1, 1);
            p1 += __shfl_xor_sync(0xffffffffu, p1, 2);
            p1 += __shfl_xor_sync(0xffffffffu, p1, 4);
            if (wr) { aw[0][seg][k] = p0 * scale; aw[0][4 + seg][k] = p1 * scale; }
        } else if (wr) {
            aw[0][seg][k] = NEGV; aw[0][4 + seg][k] = NEGV;
        }

        if (!m1) {
            float p0 = qb0.x * (a0.x + t10.x) + qb0.y * (a0.y + t10.y)
                     + qb0.z * (a0.z + t10.z) + qb0.w * (a0.w + t10.w);
            float p1 = qb1.x * (a1.x + t11.x) + qb1.y * (a1.y + t11.y)
                     + qb1.z * (a1.z + t11.z) + qb1.w * (a1.w + t11.w);
            p0 += __shfl_xor_sync(0xffffffffu, p0, 1);
            p0 += __shfl_xor_sync(0xffffffffu, p0, 2);
            p0 += __shfl_xor_sync(0xffffffffu, p0, 4);
            p1 += __shfl_xor_sync(0xffffffffu, p1, 1);
            p1 += __shfl_xor_sync(0xffffffffu, p1, 2);
            p1 += __shfl_xor_sync(0xffffffffu, p1, 4);
            if (wr) { aw[1][seg][k] = p0 * scale; aw[1][4 + seg][k] = p1 * scale; }
        } else if (wr) {
            aw[1][seg][k] = NEGV; aw[1][4 + seg][k] = NEGV;
        }
    }
    __syncthreads();

    // ---- Phase 2: per-head softmax (warp w = head w), both queries ----
    #pragma unroll
    for (int qi = 0; qi < 2; qi++) {
        float vals[7];
        float mx = -3.402823466e38f;
        #pragma unroll
        for (int i = 0; i < 7; i++) {
            const int k = l + 32 * i;
            float v = (k < LL) ? aw[qi][w][k] : -3.402823466e38f;
            vals[i] = v;
            mx = fmaxf(mx, v);
        }
        #pragma unroll
        for (int o = 16; o > 0; o >>= 1)
            mx = fmaxf(mx, __shfl_xor_sync(0xffffffffu, mx, o));
        float s = 0.f;
        #pragma unroll
        for (int i = 0; i < 7; i++) {
            const int k = l + 32 * i;
            if (k < LL) { vals[i] = __expf(vals[i] - mx); s += vals[i]; }
        }
        #pragma unroll
        for (int o = 16; o > 0; o >>= 1)
            s += __shfl_xor_sync(0xffffffffu, s, o);
        const float inv = 1.0f / s;
        #pragma unroll
        for (int i = 0; i < 7; i++) {
            const int k = l + 32 * i;
            if (k < LL) aw[qi][w][k] = vals[i] * inv;
        }
    }
    __syncthreads();

    // ---- Phase 3: weighted value accumulation (float4 per thread) ----
    const int j  = tid & 63;       // channel group: channels [4j, 4j+4)
    const int kq = tid >> 6;       // k offset mod 4 (uniform per warp)
    const int h3 = j >> 3;         // head of channels 4j..4j+3
    const float* __restrict__ Vs   = g_Vs + (size_t)(b * LL) * HIDD;
    const float* __restrict__ TMV0 = tmV + (size_t)(b * LL + q0) * LL * HIDD;
    const float* __restrict__ TMV1 = tmV + (size_t)(b * LL + q1) * LL * HIDD;

    float4 acc0 = make_float4(0.f, 0.f, 0.f, 0.f);
    float4 acc1 = make_float4(0.f, 0.f, 0.f, 0.f);
    #pragma unroll 4
    for (int i = 0; i < LL / 4; i++) {
        const int k = kq + 4 * i;
        const float w0 = aw[0][h3][k];
        const float w1 = aw[1][h3][k];
        if ((w0 != 0.f) | (w1 != 0.f)) {   // exp underflows to exact 0 when masked
            const float4 v = *(const float4*)(Vs + k * HIDD + 4 * j);
            if (w0 != 0.f) {
                const float4 t = __ldcs((const float4*)(TMV0 + (size_t)k * HIDD + 4 * j));
                acc0.x += w0 * (v.x + t.x);
                acc0.y += w0 * (v.y + t.y);
                acc0.z += w0 * (v.z + t.z);
                acc0.w += w0 * (v.w + t.w);
            }
            if (w1 != 0.f) {
                const float4 t = __ldcs((const float4*)(TMV1 + (size_t)k * HIDD + 4 * j));
                acc1.x += w1 * (v.x + t.x);
                acc1.y += w1 * (v.y + t.y);
                acc1.z += w1 * (v.z + t.z);
                acc1.w += w1 * (v.w + t.w);
            }
        }
    }
    red[0][kq][j] = acc0;
    red[1][kq][j] = acc1;
    __syncthreads();
    if (kq < 2) {
        const int qi = kq;
        float4 r0 = red[qi][0][j], r1 = red[qi][1][j];
        float4 r2 = red[qi][2][j], r3 = red[qi][3][j];
        float4 o;
        o.x = r0.x + r1.x + r2.x + r3.x;
        o.y = r0.y + r1.y + r2.y + r3.y;
        o.z = r0.z + r1.z + r2.z + r3.z;
        o.w = r0.w + r1.w + r2.w + r3.w;
        *(float4*)(out + (size_t)(b * LL + q0 + qi) * HIDD + 4 * j) = o;
    }
}

// ---------------------------------------------------------------------------
extern "C" void kernel_launch(void* const* d_in, const int* in_sizes, int n_in,
                              void* d_out, int out_size)
{
    const float* queries   = (const float*)d_in[0];
    const float* keys      = (const float*)d_in[1];
    const int*   time_mask = (const int*)  d_in[2];
    const int*   attn_mask = (const int*)  d_in[3];
    const float* tmK       = (const float*)d_in[4];
    const float* tmV       = (const float*)d_in[5];
    const float* apK       = (const float*)d_in[6];
    const float* apV       = (const float*)d_in[7];
    // d_in[8] = time_attn (unused by the forward pass)
    const float* Wq        = (const float*)d_in[9];
    const float* bq        = (const float*)d_in[10];
    const float* Wk        = (const float*)d_in[11];
    const float* bk        = (const float*)d_in[12];
    const float* Wv        = (const float*)d_in[13];
    const float* bv        = (const float*)d_in[14];
    float* out = (float*)d_out;

    dim3 pgrid(1600 / 64, HIDD / 64, 3);   // (25, 4, 3)
    proj_kernel<<<pgrid, 256>>>(queries, keys, Wq, bq, Wk, bk, Wv, bv, apK, apV);

    dim3 agrid(LL / 2, BB);                 // (100, 8)
    attn_kernel<<<agrid, 256>>>(tmK, tmV, time_mask, attn_mask, out);
}

// round 11
// speedup vs baseline: 1.2055x; 1.2055x over previous
#include <cuda_runtime.h>

// Shapes (fixed for this problem)
#define BB   8
#define LL   200
#define HIDD 256
#define NH   8
#define DHH  32
#define NEGV (-4294967295.0f)   // -2^32 + 1, matches reference padding value

// Scratch (device globals: allocation-free rule)
__device__ float g_Qp[BB * LL * HIDD];
__device__ float g_Ks[BB * LL * HIDD];   // K-proj + abs_pos_K  (folded)
__device__ float g_Vs[BB * LL * HIDD];   // V-proj + abs_pos_V  (folded)

// ---------------------------------------------------------------------------
// Projection GEMM:  Y = X @ W^T + bias (+ optional abs_pos fold)
// M=1600, N=256, K=256.  grid (25, 4, 3): z selects Q/K/V. block = 256 thr.
// BM=BN=64, BK=32 (8 tile steps, 16 barriers). 4x4 register micro-tile.
// ---------------------------------------------------------------------------
__global__ __launch_bounds__(256) void proj_kernel(
    const float* __restrict__ queries, const float* __restrict__ keys,
    const float* __restrict__ Wq, const float* __restrict__ bq,
    const float* __restrict__ Wk, const float* __restrict__ bk,
    const float* __restrict__ Wv, const float* __restrict__ bv,
    const float* __restrict__ apK, const float* __restrict__ apV)
{
    const int which = blockIdx.z;
    const float* X    = (which == 0) ? queries : keys;
    const float* W    = (which == 0) ? Wq : (which == 1) ? Wk : Wv;
    const float* bias = (which == 0) ? bq : (which == 1) ? bk : bv;
    const float* fold = (which == 0) ? (const float*)0 : (which == 1) ? apK : apV;
    float* Y          = (which == 0) ? g_Qp : (which == 1) ? g_Ks : g_Vs;

    __shared__ float As[32][65];   // [k][m], padded
    __shared__ float Bs[32][65];   // [k][n], padded

    const int tid = threadIdx.x;
    const int tx = tid & 15, ty = tid >> 4;
    const int row0 = blockIdx.x * 64, col0 = blockIdx.y * 64;

    const int lr  = tid >> 2;          // 0..63 (tile row to load)
    const int lc8 = (tid & 3) * 8;     // 0,8,16,24 (k-offset)

    float acc[4][4] = {};

    for (int kt = 0; kt < HIDD; kt += 32) {
        float4 av0 = *(const float4*)&X[(row0 + lr) * HIDD + kt + lc8];
        float4 av1 = *(const float4*)&X[(row0 + lr) * HIDD + kt + lc8 + 4];
        float4 bw0 = *(const float4*)&W[(col0 + lr) * HIDD + kt + lc8];
        float4 bw1 = *(const float4*)&W[(col0 + lr) * HIDD + kt + lc8 + 4];
        As[lc8 + 0][lr] = av0.x;  As[lc8 + 1][lr] = av0.y;
        As[lc8 + 2][lr] = av0.z;  As[lc8 + 3][lr] = av0.w;
        As[lc8 + 4][lr] = av1.x;  As[lc8 + 5][lr] = av1.y;
        As[lc8 + 6][lr] = av1.z;  As[lc8 + 7][lr] = av1.w;
        Bs[lc8 + 0][lr] = bw0.x;  Bs[lc8 + 1][lr] = bw0.y;
        Bs[lc8 + 2][lr] = bw0.z;  Bs[lc8 + 3][lr] = bw0.w;
        Bs[lc8 + 4][lr] = bw1.x;  Bs[lc8 + 5][lr] = bw1.y;
        Bs[lc8 + 6][lr] = bw1.z;  Bs[lc8 + 7][lr] = bw1.w;
        __syncthreads();
        #pragma unroll
        for (int kk = 0; kk < 32; kk++) {
            float a[4], b[4];
            #pragma unroll
            for (int i = 0; i < 4; i++) a[i] = As[kk][ty * 4 + i];
            #pragma unroll
            for (int j = 0; j < 4; j++) b[j] = Bs[kk][tx * 4 + j];
            #pragma unroll
            for (int i = 0; i < 4; i++)
                #pragma unroll
                for (int j = 0; j < 4; j++)
                    acc[i][j] += a[i] * b[j];
        }
        __syncthreads();
    }

    #pragma unroll
    for (int i = 0; i < 4; i++) {
        const int r = row0 + ty * 4 + i;
        #pragma unroll
        for (int j = 0; j < 4; j++) {
            const int cc = col0 + tx * 4 + j;
            float v = acc[i][j] + bias[cc];
            if (fold) v += fold[r * HIDD + cc];
            Y[r * HIDD + cc] = v;
        }
    }
}

// ---------------------------------------------------------------------------
// Attention: one CTA per (q, b); q remapped heaviest-first. 256 threads.
// Unmasked k's compacted into klist (ballot scan, deterministic order) so all
// loop loads are unconditional -> full pipelining. aw pre-filled with NEGV.
// Phase 1: warp w handles klist[w + 8i]; lane holds 2 float4 of the 1KB row;
//   segmented 8-lane shuffle reduction yields all 8 heads per k.
// Phase 2: per-head softmax (warp w = head w).
// Phase 3: thread owns float4 channel group j, compact k strided mod 4;
//   identity-list fallback when every k is masked (uniform softmax case).
// ---------------------------------------------------------------------------
__global__ __launch_bounds__(256) void attn_kernel(
    const float* __restrict__ tmK, const float* __restrict__ tmV,
    const int* __restrict__ time_mask, const int* __restrict__ attn_mask,
    float* __restrict__ out)
{
    const int q = (LL - 1) - blockIdx.x;   // heaviest (largest k-range) first
    const int b = blockIdx.y;
    const int tid = threadIdx.x;
    const int w = tid >> 5;        // warp
    const int l = tid & 31;        // lane

    __shared__ float aw[NH][LL];
    __shared__ int   klist[LL];
    __shared__ int   s_nk;
    __shared__ float4 red[4][64];

    // Pre-fill logits with the masked value
    for (int idx = tid; idx < NH * LL; idx += 256)
        (&aw[0][0])[idx] = NEGV;

    // Warp 0: compact unmasked k indices (order-preserving ballot scan)
    if (w == 0) {
        const int tmw = time_mask[b * LL + q];
        int base = 0;
        #pragma unroll
        for (int c0 = 0; c0 < 224; c0 += 32) {
            const int k = c0 + l;
            const bool un = (k < LL) && (tmw == 0) && (attn_mask[q * LL + k] == 0);
            const unsigned bal = __ballot_sync(0xffffffffu, un);
            if (un) klist[base + __popc(bal & ((1u << l) - 1u))] = k;
            base += __popc(bal);
        }
        if (l == 0) s_nk = base;
    }
    __syncthreads();
    const int nk = s_nk;

    const float* __restrict__ Qp = g_Qp + (size_t)(b * LL + q) * HIDD;
    const float4 q0 = *(const float4*)(Qp + 4 * l);
    const float4 q1 = *(const float4*)(Qp + 128 + 4 * l);

    const float* __restrict__ Ks  = g_Ks + (size_t)(b * LL) * HIDD;
    const float* __restrict__ TMK = tmK + (size_t)(b * LL + q) * LL * HIDD;
    const float  scale = 0.17677669529663687f;   // 1/sqrt(32)

    const int  seg = l >> 3;           // 0..3: p0 -> head seg, p1 -> head 4+seg
    const bool wr  = (l & 7) == 0;

    // ---- Phase 1: logits over compacted k's (unconditional loads) ----
    #pragma unroll 2
    for (int i = w; i < nk; i += 8) {
        const int k = klist[i];
        const float4 a0 = *(const float4*)(Ks + k * HIDD + 4 * l);
        const float4 a1 = *(const float4*)(Ks + k * HIDD + 128 + 4 * l);
        const float4 t0 = __ldcs((const float4*)(TMK + (size_t)k * HIDD + 4 * l));
        const float4 t1 = __ldcs((const float4*)(TMK + (size_t)k * HIDD + 128 + 4 * l));
        float p0 = q0.x * (a0.x + t0.x) + q0.y * (a0.y + t0.y)
                 + q0.z * (a0.z + t0.z) + q0.w * (a0.w + t0.w);
        float p1 = q1.x * (a1.x + t1.x) + q1.y * (a1.y + t1.y)
                 + q1.z * (a1.z + t1.z) + q1.w * (a1.w + t1.w);
        p0 += __shfl_xor_sync(0xffffffffu, p0, 1);
        p0 += __shfl_xor_sync(0xffffffffu, p0, 2);
        p0 += __shfl_xor_sync(0xffffffffu, p0, 4);
        p1 += __shfl_xor_sync(0xffffffffu, p1, 1);
        p1 += __shfl_xor_sync(0xffffffffu, p1, 2);
        p1 += __shfl_xor_sync(0xffffffffu, p1, 4);
        if (wr) { aw[seg][k] = p0 * scale; aw[4 + seg][k] = p1 * scale; }
    }
    __syncthreads();

    // ---- Phase 2: per-head softmax (warp w = head w) ----
    {
        float vals[7];
        float mx = -3.402823466e38f;
        #pragma unroll
        for (int i = 0; i < 7; i++) {
            const int k = l + 32 * i;
            float v = (k < LL) ? aw[w][k] : -3.402823466e38f;
            vals[i] = v;
            mx = fmaxf(mx, v);
        }
        #pragma unroll
        for (int o = 16; o > 0; o >>= 1)
            mx = fmaxf(mx, __shfl_xor_sync(0xffffffffu, mx, o));
        float s = 0.f;
        #pragma unroll
        for (int i = 0; i < 7; i++) {
            const int k = l + 32 * i;
            if (k < LL) { vals[i] = __expf(vals[i] - mx); s += vals[i]; }
        }
        #pragma unroll
        for (int o = 16; o > 0; o >>= 1)
            s += __shfl_xor_sync(0xffffffffu, s, o);
        const float inv = 1.0f / s;
        #pragma unroll
        for (int i = 0; i < 7; i++) {
            const int k = l + 32 * i;
            if (k < LL) aw[w][k] = vals[i] * inv;
        }
    }
    __syncthreads();

    // Degenerate fully-masked row: softmax is uniform over ALL k -> phase 3
    // must visit every k. Swap in an identity list. (Block-uniform branch.)
    int nk3 = nk;
    if (nk3 == 0) {
        for (int i = tid; i < LL; i += 256) klist[i] = i;
        nk3 = LL;
        __syncthreads();
    }

    // ---- Phase 3: weighted value accumulation (float4 per thread) ----
    const int j  = tid & 63;       // channel group: channels [4j, 4j+4)
    const int kq = tid >> 6;       // k offset mod 4 (uniform per warp)
    const int h3 = j >> 3;         // head of channels 4j..4j+3
    const float* __restrict__ Vs  = g_Vs + (size_t)(b * LL) * HIDD;
    const float* __restrict__ TMV = tmV + (size_t)(b * LL + q) * LL * HIDD;

    float4 acc = make_float4(0.f, 0.f, 0.f, 0.f);
    #pragma unroll 4
    for (int i = kq; i < nk3; i += 4) {
        const int k = klist[i];
        const float wgt = aw[h3][k];
        const float4 v = *(const float4*)(Vs + k * HIDD + 4 * j);
        const float4 t = __ldcs((const float4*)(TMV + (size_t)k * HIDD + 4 * j));
        acc.x += wgt * (v.x + t.x);
        acc.y += wgt * (v.y + t.y);
        acc.z += wgt * (v.z + t.z);
        acc.w += wgt * (v.w + t.w);
    }
    red[kq][j] = acc;
    __syncthreads();
    if (kq == 0) {
        const float4 r1 = red[1][j], r2 = red[2][j], r3 = red[3][j];
        acc.x += r1.x + r2.x + r3.x;
        acc.y += r1.y + r2.y + r3.y;
        acc.z += r1.z + r2.z + r3.z;
        acc.w += r1.w + r2.w + r3.w;
        *(float4*)(out + (size_t)(b * LL + q) * HIDD + 4 * j) = acc;
    }
}

// ---------------------------------------------------------------------------
extern "C" void kernel_launch(void* const* d_in, const int* in_sizes, int n_in,
                              void* d_out, int out_size)
{
    const float* queries   = (const float*)d_in[0];
    const float* keys      = (const float*)d_in[1];
    const int*   time_mask = (const int*)  d_in[2];
    const int*   attn_mask = (const int*)  d_in[3];
    const float* tmK       = (const float*)d_in[4];
    const float* tmV       = (const float*)d_in[5];
    const float* apK       = (const float*)d_in[6];
    const float* apV       = (const float*)d_in[7];
    // d_in[8] = time_attn (unused by the forward pass)
    const float* Wq        = (const float*)d_in[9];
    const float* bq        = (const float*)d_in[10];
    const float* Wk        = (const float*)d_in[11];
    const float* bk        = (const float*)d_in[12];
    const float* Wv        = (const float*)d_in[13];
    const float* bv        = (const float*)d_in[14];
    float* out = (float*)d_out;

    dim3 pgrid(1600 / 64, HIDD / 64, 3);   // (25, 4, 3)
    proj_kernel<<<pgrid, 256>>>(queries, keys, Wq, bq, Wk, bk, Wv, bv, apK, apV);

    dim3 agrid(LL, BB);                     // (200, 8)
    attn_kernel<<<agrid, 256>>>(tmK, tmV, time_mask, attn_mask, out);
}